// round 6
// baseline (speedup 1.0000x reference)
#include <cuda_runtime.h>
#include <cuda_bf16.h>
#include <cstdint>
#include <math.h>

#define B_      1024
#define H_      256
#define G3_     768
#define LPRE    60
#define LFWD    80
#define ML_     80

// ---------------- static device scratch (no allocation) ----------------
__device__ float g_catpre64[LPRE * B_ * 64];
__device__ float g_Mf64[G3_ * 64];
__device__ float g_gibias[G3_];
__device__ float g_GIenc[LPRE * B_ * G3_];
__device__ float g_ENC[LPRE * B_ * H_];
__device__ float g_M1[H_ * H_];
__device__ float g_c1[H_];
__device__ float g_c0fix[H_];
__device__ float g_Xe[LFWD * B_ * H_];
__device__ float g_Wstack[2 * G3_ * H_];
__device__ float g_bstack[2 * G3_];
__device__ float g_ctx[B_ * H_];
__device__ float g_g[B_ * H_];
__device__ float g_gigh[B_ * 2 * G3_];
__device__ float g_gh[B_ * G3_];
__device__ float g_hbuf[2][B_ * H_];
__device__ float g_Hall[LFWD * B_ * H_];
__device__ float g_We_pad[128 * H_];
__device__ float g_Wh_pad[128 * H_];
__device__ float g_Wfuse[128 * H_];
__device__ float g_abias_pad[128];
__device__ float g_corr_l[128];
__device__ float g_Wck[H_ * 512];
__device__ float g_bias0c[H_];
__device__ float g_XL[LFWD * B_ * 128];
__device__ float g_XC[LFWD * B_ * H_];

// ================= helpers =================
__device__ __forceinline__ uint32_t smem_u32(const void* p) {
    uint32_t a;
    asm("{ .reg .u64 t; cvta.to.shared.u64 t, %1; cvt.u32.u64 %0, t; }" : "=r"(a) : "l"(p));
    return a;
}

#define STS128(r0, r1, r2, r3, smem_addr) \
    asm volatile("st.shared.v4.b32 [%0], {%1, %2, %3, %4};" \
        :: "r"(smem_addr), "r"(r0), "r"(r1), "r"(r2), "r"(r3) : "memory")

#define LDSM4(r0, r1, r2, r3, addr) \
    asm volatile("ldmatrix.sync.aligned.m8n8.x4.shared.b16 {%0,%1,%2,%3}, [%4];" \
        : "=r"(r0), "=r"(r1), "=r"(r2), "=r"(r3) : "r"(addr))

#define MMA16816(d, a, b) \
    asm volatile("mma.sync.aligned.m16n8k16.row.col.f32.bf16.bf16.f32 " \
        "{%0,%1,%2,%3},{%4,%5,%6,%7},{%8,%9},{%0,%1,%2,%3};" \
        : "+f"((d)[0]), "+f"((d)[1]), "+f"((d)[2]), "+f"((d)[3]) \
        : "r"((a)[0]), "r"((a)[1]), "r"((a)[2]), "r"((a)[3]), "r"((b)[0]), "r"((b)[1]))

__device__ __forceinline__ void cvt_hl(float x, float y, uint32_t& h, uint32_t& l) {
    __nv_bfloat162 hb = __floats2bfloat162_rn(x, y);
    float rx = x - __low2float(hb);
    float ry = y - __high2float(hb);
    __nv_bfloat162 lb = __floats2bfloat162_rn(rx, ry);
    h = *reinterpret_cast<uint32_t*>(&hb);
    l = *reinterpret_cast<uint32_t*>(&lb);
}

__device__ __forceinline__ uint32_t swz(int r, int c) {
    return (uint32_t)(r * 64 + ((c ^ ((r >> 1) & 3)) << 4));
}

__device__ __forceinline__ void ldg16(const float* __restrict__ p, float* f) {
#pragma unroll
    for (int i = 0; i < 4; i++) {
        float4 v = *(const float4*)(p + 4 * i);
        f[4 * i + 0] = v.x; f[4 * i + 1] = v.y; f[4 * i + 2] = v.z; f[4 * i + 3] = v.w;
    }
}

__device__ __forceinline__ void sts_half(uint32_t sh, uint32_t sl, int row, int c0, const float* f) {
    uint32_t h[8], l[8];
#pragma unroll
    for (int i = 0; i < 8; i++) cvt_hl(f[2 * i], f[2 * i + 1], h[i], l[i]);
    uint32_t o0 = swz(row, c0), o1 = swz(row, c0 + 1);
    STS128(h[0], h[1], h[2], h[3], sh + o0);
    STS128(h[4], h[5], h[6], h[7], sh + o1);
    STS128(l[0], l[1], l[2], l[3], sl + o0);
    STS128(l[4], l[5], l[6], l[7], sl + o1);
}

// ================= BM=128 mma GEMM (prep, big-M) =================
#define MG_SMEM (2 * 32768)
#define OFF_AH 0u
#define OFF_AL 8192u
#define OFF_BH 16384u
#define OFF_BL 24576u

__global__ __launch_bounds__(256, 1) void mmagemm_kernel(
    const float* __restrict__ A0, int lda0,
    const float* __restrict__ W, int ldw,
    const float* __restrict__ bias,
    float* __restrict__ C, int ldc,
    int M, int N, int K)
{
    extern __shared__ char dsm[];
    uint32_t sb = smem_u32(dsm);
    int tid = threadIdx.x, lane = tid & 31, wid = tid >> 5;
    int bm = blockIdx.y * 128, bn = blockIdx.x * 128;
    int warpM = wid & 3, warpN = wid >> 2;

    int lrow = tid >> 1, lhalf = tid & 1;
    const float* rowA = A0 + (size_t)(bm + lrow) * lda0 + lhalf * 16;
    const float* bp = W + (size_t)(bn + lrow) * ldw + lhalf * 16;

    float acc[2][8][4];
#pragma unroll
    for (int i = 0; i < 2; i++)
#pragma unroll
        for (int j = 0; j < 8; j++)
#pragma unroll
            for (int q = 0; q < 4; q++) acc[i][j][q] = 0.f;

    float fa[16], fb[16];
    int nk = K >> 5;

    ldg16(rowA, fa);
    ldg16(bp, fb);
    sts_half(sb + OFF_AH, sb + OFF_AL, lrow, lhalf * 2, fa);
    sts_half(sb + OFF_BH, sb + OFF_BL, lrow, lhalf * 2, fb);
    __syncthreads();

    for (int i = 0; i < nk; i++) {
        if (i + 1 < nk) {
            ldg16(rowA + (i + 1) * 32, fa);
            ldg16(bp + (i + 1) * 32, fb);
        }
        uint32_t st = sb + (uint32_t)(i & 1) * 32768u;
#pragma unroll
        for (int ks = 0; ks < 2; ks++) {
            uint32_t ah[2][4], al[2][4], bh[8][2], bl[8][2];
#pragma unroll
            for (int mf = 0; mf < 2; mf++) {
                int r = warpM * 32 + mf * 16 + (lane & 15);
                int c = ks * 2 + (lane >> 4);
                uint32_t o = swz(r, c);
                LDSM4(ah[mf][0], ah[mf][1], ah[mf][2], ah[mf][3], st + OFF_AH + o);
                LDSM4(al[mf][0], al[mf][1], al[mf][2], al[mf][3], st + OFF_AL + o);
            }
#pragma unroll
            for (int p = 0; p < 4; p++) {
                int r = warpN * 64 + p * 16 + (lane & 7) + ((lane >> 4) << 3);
                int c = ks * 2 + ((lane >> 3) & 1);
                uint32_t o = swz(r, c);
                LDSM4(bh[2 * p][0], bh[2 * p][1], bh[2 * p + 1][0], bh[2 * p + 1][1], st + OFF_BH + o);
                LDSM4(bl[2 * p][0], bl[2 * p][1], bl[2 * p + 1][0], bl[2 * p + 1][1], st + OFF_BL + o);
            }
#pragma unroll
            for (int mf = 0; mf < 2; mf++)
#pragma unroll
                for (int nf = 0; nf < 8; nf++) {
                    MMA16816(acc[mf][nf], ah[mf], bh[nf]);
                    MMA16816(acc[mf][nf], ah[mf], bl[nf]);
                    MMA16816(acc[mf][nf], al[mf], bh[nf]);
                }
        }
        if (i + 1 < nk) {
            uint32_t st2 = sb + (uint32_t)((i + 1) & 1) * 32768u;
            sts_half(st2 + OFF_AH, st2 + OFF_AL, lrow, lhalf * 2, fa);
            sts_half(st2 + OFF_BH, st2 + OFF_BL, lrow, lhalf * 2, fb);
            __syncthreads();
        }
    }

#pragma unroll
    for (int mf = 0; mf < 2; mf++)
#pragma unroll
        for (int nf = 0; nf < 8; nf++) {
            int m0 = bm + warpM * 32 + mf * 16 + (lane >> 2);
            int n = bn + warpN * 64 + nf * 8 + (lane & 3) * 2;
            float b0 = 0.f, b1 = 0.f;
            if (bias) { b0 = bias[n]; b1 = bias[n + 1]; }
#pragma unroll
            for (int hh = 0; hh < 2; hh++) {
                int m = m0 + hh * 8;
                float2 vv = make_float2(acc[mf][nf][2 * hh] + b0, acc[mf][nf][2 * hh + 1] + b1);
                *(float2*)(C + (size_t)m * ldc + n) = vv;
            }
        }
}

// ================= BM=64 mma GEMM (serial path: more blocks) =================
// stage: AH 4KB | AL 4KB | BH 8KB | BL 8KB = 24KB; 2 stages = 48KB
#define MG64_SMEM (2 * 24576)
#define O64_AH 0u
#define O64_AL 4096u
#define O64_BH 8192u
#define O64_BL 16384u

__global__ __launch_bounds__(256, 1) void mmagemm64_kernel(
    const float* __restrict__ A0, const float* __restrict__ A1, int splitN, int lda0,
    const float* __restrict__ Ak, int ksplit, int ldak,
    const float* __restrict__ W, int ldw,
    const float* __restrict__ bias,
    const float* __restrict__ addmat, int ldadd,
    float* __restrict__ C, int ldc,
    int M, int N, int K, int act)
{
    extern __shared__ char dsm[];
    uint32_t sb = smem_u32(dsm);
    int tid = threadIdx.x, lane = tid & 31, wid = tid >> 5;
    int bm = blockIdx.y * 64, bn = blockIdx.x * 128;
    const float* __restrict__ A = (bn < splitN) ? A0 : A1;
    int warpM = wid & 1, warpN = wid >> 1;

    int lrow = tid >> 1, lhalf = tid & 1;          // B: 128 rows, 2 threads/row
    int arow = (tid & 127) >> 1;                   // A: 64 rows (threads 0..127)
    bool doA = tid < 128;
    const float* rowA = A + (size_t)(bm + arow) * lda0 + lhalf * 16;
    const float* rowAk = Ak ? Ak + (size_t)(bm + arow) * ldak + lhalf * 16 : nullptr;
    const float* bp = W + (size_t)(bn + lrow) * ldw + lhalf * 16;

    float acc[2][4][4];
#pragma unroll
    for (int i = 0; i < 2; i++)
#pragma unroll
        for (int j = 0; j < 4; j++)
#pragma unroll
            for (int q = 0; q < 4; q++) acc[i][j][q] = 0.f;

    float fa[16], fb[16];
    int nk = K >> 5;

    {
        ldg16(bp, fb);
        if (doA) {
            const float* ap0 = (0 < ksplit) ? rowA : rowAk;
            ldg16(ap0, fa);
        }
        sts_half(sb + O64_BH, sb + O64_BL, lrow, lhalf * 2, fb);
        if (doA) sts_half(sb + O64_AH, sb + O64_AL, arow, lhalf * 2, fa);
    }
    __syncthreads();

    for (int i = 0; i < nk; i++) {
        if (i + 1 < nk) {
            int kk = (i + 1) * 32;
            ldg16(bp + kk, fb);
            if (doA) {
                const float* apn = (kk < ksplit) ? (rowA + kk) : (rowAk + (kk - ksplit));
                ldg16(apn, fa);
            }
        }
        uint32_t st = sb + (uint32_t)(i & 1) * 24576u;
#pragma unroll
        for (int ks = 0; ks < 2; ks++) {
            uint32_t ah[2][4], al[2][4], bh[4][2], bl[4][2];
#pragma unroll
            for (int mf = 0; mf < 2; mf++) {
                int r = warpM * 32 + mf * 16 + (lane & 15);
                int c = ks * 2 + (lane >> 4);
                uint32_t o = swz(r, c);
                LDSM4(ah[mf][0], ah[mf][1], ah[mf][2], ah[mf][3], st + O64_AH + o);
                LDSM4(al[mf][0], al[mf][1], al[mf][2], al[mf][3], st + O64_AL + o);
            }
#pragma unroll
            for (int p = 0; p < 2; p++) {
                int r = warpN * 32 + p * 16 + (lane & 7) + ((lane >> 4) << 3);
                int c = ks * 2 + ((lane >> 3) & 1);
                uint32_t o = swz(r, c);
                LDSM4(bh[2 * p][0], bh[2 * p][1], bh[2 * p + 1][0], bh[2 * p + 1][1], st + O64_BH + o);
                LDSM4(bl[2 * p][0], bl[2 * p][1], bl[2 * p + 1][0], bl[2 * p + 1][1], st + O64_BL + o);
            }
#pragma unroll
            for (int mf = 0; mf < 2; mf++)
#pragma unroll
                for (int nf = 0; nf < 4; nf++) {
                    MMA16816(acc[mf][nf], ah[mf], bh[nf]);
                    MMA16816(acc[mf][nf], ah[mf], bl[nf]);
                    MMA16816(acc[mf][nf], al[mf], bh[nf]);
                }
        }
        if (i + 1 < nk) {
            uint32_t st2 = sb + (uint32_t)((i + 1) & 1) * 24576u;
            sts_half(st2 + O64_BH, st2 + O64_BL, lrow, lhalf * 2, fb);
            if (doA) sts_half(st2 + O64_AH, st2 + O64_AL, arow, lhalf * 2, fa);
            __syncthreads();
        }
    }

#pragma unroll
    for (int mf = 0; mf < 2; mf++)
#pragma unroll
        for (int nf = 0; nf < 4; nf++) {
            int m0 = bm + warpM * 32 + mf * 16 + (lane >> 2);
            int n = bn + warpN * 32 + nf * 8 + (lane & 3) * 2;
            float b0 = 0.f, b1 = 0.f;
            if (bias) { b0 = bias[n]; b1 = bias[n + 1]; }
#pragma unroll
            for (int hh = 0; hh < 2; hh++) {
                int m = m0 + hh * 8;
                float v0 = acc[mf][nf][2 * hh] + b0;
                float v1 = acc[mf][nf][2 * hh + 1] + b1;
                if (addmat) {
                    const float* am = addmat + (size_t)m * ldadd + n;
                    v0 += am[0]; v1 += am[1];
                }
                if (act == 1) { v0 = tanhf(v0); v1 = tanhf(v1); }
                float2 vv = make_float2(v0, v1);
                *(float2*)(C + (size_t)m * ldc + n) = vv;
            }
        }
}

// ---------------- SIMT fp32 GEMM (final output) ----------------
__global__ __launch_bounds__(256) void gemm_kernel(
    const float* __restrict__ A, const float* __restrict__ W, int ldw,
    const float* __restrict__ bias,
    float* __restrict__ C, int ldc,
    int M, int N, int K)
{
    __shared__ float As[16][64];
    __shared__ float Bs[16][64];
    int bn = blockIdx.x * 64;
    int bm = blockIdx.y * 64;

    int tid = threadIdx.x;
    int tx = tid & 15, ty = tid >> 4;
    int lr = tid >> 2;
    int lk = (tid & 3) * 4;

    float acc[4][4];
#pragma unroll
    for (int i = 0; i < 4; i++)
#pragma unroll
        for (int j = 0; j < 4; j++) acc[i][j] = 0.f;

    for (int k0 = 0; k0 < K; k0 += 16) {
        float4 a4 = *(const float4*)(A + (size_t)(bm + lr) * K + k0 + lk);
        As[lk + 0][lr] = a4.x; As[lk + 1][lr] = a4.y;
        As[lk + 2][lr] = a4.z; As[lk + 3][lr] = a4.w;
        float4 b4 = make_float4(0.f, 0.f, 0.f, 0.f);
        if (bn + lr < N)
            b4 = *(const float4*)(W + (size_t)(bn + lr) * ldw + k0 + lk);
        Bs[lk + 0][lr] = b4.x; Bs[lk + 1][lr] = b4.y;
        Bs[lk + 2][lr] = b4.z; Bs[lk + 3][lr] = b4.w;
        __syncthreads();
#pragma unroll
        for (int kk = 0; kk < 16; kk++) {
            float ra[4], rb[4];
#pragma unroll
            for (int i = 0; i < 4; i++) ra[i] = As[kk][ty * 4 + i];
#pragma unroll
            for (int j = 0; j < 4; j++) rb[j] = Bs[kk][tx * 4 + j];
#pragma unroll
            for (int i = 0; i < 4; i++)
#pragma unroll
                for (int j = 0; j < 4; j++) acc[i][j] += ra[i] * rb[j];
        }
        __syncthreads();
    }

#pragma unroll
    for (int i = 0; i < 4; i++) {
        int m = bm + ty * 4 + i;
#pragma unroll
        for (int j = 0; j < 4; j++) {
            int n = bn + tx * 4 + j;
            if (n < N)
                C[(size_t)m * ldc + n] = acc[i][j] + bias[n];
        }
    }
}

// ---------------- prep kernels ----------------
__global__ void pack_catpre_kernel(const float* __restrict__ px, const float* __restrict__ py,
                                   float* __restrict__ out)
{
    int idx = blockIdx.x * 256 + threadIdx.x;
    if (idx >= LPRE * B_ * 64) return;
    int c = idx & 63;
    int tb = idx >> 6;
    float v = 0.f;
    if (c < 32) v = px[(size_t)tb * 32 + c];
    else if (c < 48) v = py[(size_t)tb * 16 + (c - 32)];
    out[idx] = v;
}

__global__ void make_Mf_kernel(const float* __restrict__ Wih, const float* __restrict__ embW,
                               const float* __restrict__ embb, const float* __restrict__ bih,
                               float* __restrict__ Mf, float* __restrict__ gib)
{
    int idx = blockIdx.x * 256 + threadIdx.x;
    if (idx < G3_ * 64) {
        int i = idx >> 6, k = idx & 63;
        float s = 0.f;
        if (k < 48)
            for (int j = 0; j < H_; j++) s += Wih[(size_t)i * H_ + j] * embW[(size_t)j * 48 + k];
        Mf[idx] = s;
    } else if (idx < G3_ * 64 + G3_) {
        int i = idx - G3_ * 64;
        float s = bih[i];
        for (int j = 0; j < H_; j++) s += Wih[(size_t)i * H_ + j] * embb[j];
        gib[i] = s;
    }
}

__global__ void make_M1_kernel(const float* __restrict__ decEmbW, const float* __restrict__ decEmbb,
                               const float* __restrict__ outW, const float* __restrict__ outb,
                               float* __restrict__ M1, float* __restrict__ c1, float* __restrict__ c0fix)
{
    int idx = blockIdx.x * 256 + threadIdx.x;
    if (idx < H_ * H_) {
        int i = idx / H_, j = idx % H_;
        float s = 0.f;
        for (int k = 0; k < 16; k++) s += decEmbW[(size_t)i * 48 + k] * outW[(size_t)k * H_ + j];
        M1[idx] = s;
    } else if (idx < H_ * H_ + H_) {
        int i = idx - H_ * H_;
        float s = 0.f;
        for (int k = 0; k < 16; k++) s += decEmbW[(size_t)i * 48 + k] * outb[k];
        c1[i] = s + decEmbb[i];
        c0fix[i] = -s;
    }
}

__global__ void stack_copy_kernel(const float* __restrict__ Wih, const float* __restrict__ Whh,
                                  const float* __restrict__ bih, const float* __restrict__ bhh,
                                  float* __restrict__ Wst, float* __restrict__ bst)
{
    int idx = blockIdx.x * 256 + threadIdx.x;
    if (idx < G3_ * H_) {
        Wst[idx] = Wih[idx];
        Wst[G3_ * H_ + idx] = Whh[idx];
    }
    if (idx < G3_) { bst[idx] = bih[idx]; bst[G3_ + idx] = bhh[idx]; }
}

__global__ void zero_h_kernel(float* __restrict__ h)
{
    int idx = blockIdx.x * 256 + threadIdx.x;
    if (idx < B_ * H_) h[idx] = 0.f;
}

__global__ void make_attnprep_kernel(const float* __restrict__ attnW, const float* __restrict__ attnb,
                                     const float* __restrict__ M1, const float* __restrict__ c0fix,
                                     float* __restrict__ We_pad, float* __restrict__ Wh_pad,
                                     float* __restrict__ Wfuse, float* __restrict__ abias_pad,
                                     float* __restrict__ corr_l)
{
    int idx = blockIdx.x * 256 + threadIdx.x;
    if (idx >= 128 * H_) return;
    int m = idx >> 8, k = idx & 255;
    float we = 0.f, wh = 0.f, wf = 0.f;
    if (m < ML_) {
        we = attnW[(size_t)m * 512 + k];
        wh = attnW[(size_t)m * 512 + 256 + k];
        float s = wh;
        for (int j = 0; j < H_; j++) s += attnW[(size_t)m * 512 + j] * M1[(size_t)j * H_ + k];
        wf = s;
    }
    We_pad[idx] = we; Wh_pad[idx] = wh; Wfuse[idx] = wf;
    if (k == 0) {
        float ab = 0.f, cl = 0.f;
        if (m < ML_) {
            ab = attnb[m];
            for (int j = 0; j < H_; j++) cl += c0fix[j] * attnW[(size_t)m * 512 + j];
        }
        abias_pad[m] = ab;
        corr_l[m] = cl;
    }
}

__global__ void make_wck_kernel(const float* __restrict__ combW, const float* __restrict__ combb,
                                const float* __restrict__ M1, const float* __restrict__ c0fix,
                                float* __restrict__ Wck, float* __restrict__ bias0c)
{
    int idx = blockIdx.x * 256 + threadIdx.x;
    if (idx >= H_ * 512) return;
    int n = idx >> 9, k = idx & 511;
    float v;
    if (k < 256) {
        v = combW[(size_t)n * 512 + 256 + k];
    } else {
        float s = 0.f;
        int kk = k - 256;
        for (int j = 0; j < H_; j++) s += combW[(size_t)n * 512 + j] * M1[(size_t)j * H_ + kk];
        v = s;
    }
    Wck[idx] = v;
    if (k == 0) {
        float s = combb[n];
        for (int j = 0; j < H_; j++) s += combW[(size_t)n * 512 + j] * c0fix[j];
        bias0c[n] = s;
    }
}

// ---------------- GRU gates (encoder + final decoder step) ----------------
__device__ __forceinline__ float sigm(float x) { return 1.f / (1.f + expf(-x)); }

__global__ __launch_bounds__(256) void gates_kernel(
    const float* __restrict__ gi, int ldgi,
    const float* __restrict__ gh, int ldgh,
    const float* __restrict__ h,
    float* __restrict__ h2, float* __restrict__ out2)
{
    int idx = blockIdx.x * 256 + threadIdx.x;
    int b = idx >> 8, j = idx & 255;
    const float* gib = gi + (size_t)b * ldgi;
    const float* ghb = gh + (size_t)b * ldgh;
    float r = sigm(gib[j] + ghb[j]);
    float z = sigm(gib[256 + j] + ghb[256 + j]);
    float n = tanhf(gib[512 + j] + r * ghb[512 + j]);
    float v = (1.f - z) * n + z * h[idx];
    h2[idx] = v;
    if (out2) out2[idx] = v;
}

// ---------------- fused decoder front: gates(t-1) + logits + softmax + ctx ------------
// grid: 64 blocks x 16 rows, 256 threads
#define AROWS 16
__global__ __launch_bounds__(256) void attnstep_kernel(
    const float* __restrict__ gigh,     // null => skip gates, use hprev directly
    const float* __restrict__ hprev,    // [B,256]
    float* __restrict__ hout,           // write h2 (if gates)
    float* __restrict__ hallout,        // write h2 (if gates)
    const float* __restrict__ Wl,       // [128,256] logits weight (Wfuse or Wh_pad)
    const float* __restrict__ lbias,    // null or corr_l
    const float* __restrict__ XLt,      // [B,128] step-t XL
    const float* __restrict__ ENC,      // [60,B,256]
    float* __restrict__ ctx)            // [B,256]
{
    __shared__ float sh[AROWS][H_];
    __shared__ float slog[AROWS][ML_];
    __shared__ float saw[AROWS][ML_];
    int tid = threadIdx.x;
    int b0 = blockIdx.x * AROWS;

    // ---- gates / load h into smem ----
    if (gigh) {
#pragma unroll
        for (int e = 0; e < AROWS * H_ / 256; e++) {
            int idx = e * 256 + tid;
            int r = idx >> 8, j = idx & 255;
            int b = b0 + r;
            const float* gib = gigh + (size_t)b * (2 * G3_);
            const float* ghb = gib + G3_;
            float rr = sigm(gib[j] + ghb[j]);
            float zz = sigm(gib[256 + j] + ghb[256 + j]);
            float nn = tanhf(gib[512 + j] + rr * ghb[512 + j]);
            float v = (1.f - zz) * nn + zz * hprev[(size_t)b * H_ + j];
            sh[r][j] = v;
            hout[(size_t)b * H_ + j] = v;
            hallout[(size_t)b * H_ + j] = v;
        }
    } else {
#pragma unroll
        for (int e = 0; e < AROWS * H_ / 256; e++) {
            int idx = e * 256 + tid;
            int r = idx >> 8, j = idx & 255;
            sh[r][j] = hprev[(size_t)(b0 + r) * H_ + j];
        }
    }
    __syncthreads();

    // ---- logits: [16 rows x 80 cols], K=256 ----
    for (int o = tid; o < AROWS * ML_; o += 256) {
        int r = o / ML_, c = o % ML_;
        const float* wr = Wl + (size_t)c * H_;
        const float* hr = sh[r];
        float acc0 = 0.f, acc1 = 0.f;
#pragma unroll 4
        for (int k = 0; k < H_; k += 2) {
            acc0 += hr[k] * wr[k];
            acc1 += hr[k + 1] * wr[k + 1];
        }
        float v = acc0 + acc1 + XLt[(size_t)(b0 + r) * 128 + c];
        if (lbias) v += lbias[c];
        slog[r][c] = v;
    }
    __syncthreads();

    // ---- softmax: warp w handles rows 2w, 2w+1 ----
    {
        int w = tid >> 5, lane = tid & 31;
#pragma unroll
        for (int rr = 0; rr < 2; rr++) {
            int r = w * 2 + rr;
            float x0 = slog[r][lane];
            float x1 = slog[r][lane + 32];
            float x2 = (lane < 16) ? slog[r][lane + 64] : -1e30f;
            float mx = fmaxf(x0, fmaxf(x1, x2));
#pragma unroll
            for (int o = 16; o; o >>= 1) mx = fmaxf(mx, __shfl_xor_sync(0xffffffffu, mx, o));
            float e0 = expf(x0 - mx), e1 = expf(x1 - mx);
            float e2 = (lane < 16) ? expf(x2 - mx) : 0.f;
            float s = e0 + e1 + e2;
#pragma unroll
            for (int o = 16; o; o >>= 1) s += __shfl_xor_sync(0xffffffffu, s, o);
            float inv = 1.f / s;
            saw[r][lane] = e0 * inv;
            saw[r][lane + 32] = e1 * inv;
            if (lane < 16) saw[r][lane + 64] = e2 * inv;
        }
    }
    __syncthreads();

    // ---- ctx: thread = column j; rows processed in pairs for ILP ----
    int j = tid;
    for (int r = 0; r < AROWS; r += 2) {
        const float* e0p = ENC + (size_t)(b0 + r) * H_ + j;
        const float* e1p = ENC + (size_t)(b0 + r + 1) * H_ + j;
        float a0 = 0.f, a1 = 0.f;
#pragma unroll 4
        for (int m = 0; m < LPRE; m++) {
            size_t off = (size_t)m * B_ * H_;
            a0 += saw[r][m] * e0p[off];
            a1 += saw[r + 1][m] * e1p[off];
        }
        ctx[(size_t)(b0 + r) * H_ + j] = a0;
        ctx[(size_t)(b0 + r + 1) * H_ + j] = a1;
    }
}

// ---------------- host launcher ----------------
static inline void run_mma128(const float* A, int lda, const float* W, int ldw,
                              const float* bias, float* C, int ldc, int M, int N, int K)
{
    dim3 grid(N / 128, M / 128);
    mmagemm_kernel<<<grid, 256, MG_SMEM>>>(A, lda, W, ldw, bias, C, ldc, M, N, K);
}

static inline void run_mma64(const float* A0, const float* A1, int splitN, int lda0,
                             const float* Ak, int ksplit, int ldak,
                             const float* W, int ldw, const float* bias,
                             const float* addmat, int ldadd,
                             float* C, int ldc, int M, int N, int K, int act)
{
    dim3 grid(N / 128, M / 64);
    mmagemm64_kernel<<<grid, 256, MG64_SMEM>>>(A0, A1, splitN, lda0, Ak, ksplit, ldak,
                                               W, ldw, bias, addmat, ldadd, C, ldc, M, N, K, act);
}

extern "C" void kernel_launch(void* const* d_in, const int* in_sizes, int n_in,
                              void* d_out, int out_size)
{
    const float* pre_x    = (const float*)d_in[0];
    const float* pre_y    = (const float*)d_in[1];
    const float* fwd_x    = (const float*)d_in[2];
    const float* encEmbW  = (const float*)d_in[3];
    const float* encEmbB  = (const float*)d_in[4];
    const float* encWih   = (const float*)d_in[5];
    const float* encWhh   = (const float*)d_in[6];
    const float* encBih   = (const float*)d_in[7];
    const float* encBhh   = (const float*)d_in[8];
    const float* decEmbW  = (const float*)d_in[9];
    const float* decEmbB  = (const float*)d_in[10];
    const float* attnW    = (const float*)d_in[11];
    const float* attnB    = (const float*)d_in[12];
    const float* combW    = (const float*)d_in[13];
    const float* combB    = (const float*)d_in[14];
    const float* decWih   = (const float*)d_in[15];
    const float* decWhh   = (const float*)d_in[16];
    const float* decBih   = (const float*)d_in[17];
    const float* decBhh   = (const float*)d_in[18];
    const float* outW     = (const float*)d_in[19];
    const float* outB     = (const float*)d_in[20];
    float* out = (float*)d_out;

    cudaFuncSetAttribute(mmagemm_kernel, cudaFuncAttributeMaxDynamicSharedMemorySize, MG_SMEM);
    cudaFuncSetAttribute(mmagemm64_kernel, cudaFuncAttributeMaxDynamicSharedMemorySize, MG64_SMEM);

    float *catpre, *Mf, *gibias, *GIenc, *ENC, *M1, *c1, *c0fix, *Xe;
    float *Wstack, *bstack, *ctx, *gbuf, *gigh, *ghb, *hb0, *hb1, *Hall;
    float *We_pad, *Wh_pad, *Wfuse, *abias_pad, *corr_l, *Wck, *bias0c, *XL, *XC;
    cudaGetSymbolAddress((void**)&catpre, g_catpre64);
    cudaGetSymbolAddress((void**)&Mf, g_Mf64);
    cudaGetSymbolAddress((void**)&gibias, g_gibias);
    cudaGetSymbolAddress((void**)&GIenc, g_GIenc);
    cudaGetSymbolAddress((void**)&ENC, g_ENC);
    cudaGetSymbolAddress((void**)&M1, g_M1);
    cudaGetSymbolAddress((void**)&c1, g_c1);
    cudaGetSymbolAddress((void**)&c0fix, g_c0fix);
    cudaGetSymbolAddress((void**)&Xe, g_Xe);
    cudaGetSymbolAddress((void**)&Wstack, g_Wstack);
    cudaGetSymbolAddress((void**)&bstack, g_bstack);
    cudaGetSymbolAddress((void**)&ctx, g_ctx);
    cudaGetSymbolAddress((void**)&gbuf, g_g);
    cudaGetSymbolAddress((void**)&gigh, g_gigh);
    cudaGetSymbolAddress((void**)&ghb, g_gh);
    cudaGetSymbolAddress((void**)&hb0, g_hbuf);
    hb1 = hb0 + B_ * H_;
    cudaGetSymbolAddress((void**)&Hall, g_Hall);
    cudaGetSymbolAddress((void**)&We_pad, g_We_pad);
    cudaGetSymbolAddress((void**)&Wh_pad, g_Wh_pad);
    cudaGetSymbolAddress((void**)&Wfuse, g_Wfuse);
    cudaGetSymbolAddress((void**)&abias_pad, g_abias_pad);
    cudaGetSymbolAddress((void**)&corr_l, g_corr_l);
    cudaGetSymbolAddress((void**)&Wck, g_Wck);
    cudaGetSymbolAddress((void**)&bias0c, g_bias0c);
    cudaGetSymbolAddress((void**)&XL, g_XL);
    cudaGetSymbolAddress((void**)&XC, g_XC);

    float* hb[2] = {hb0, hb1};

    // ---- prep ----
    pack_catpre_kernel<<<(LPRE * B_ * 64 + 255) / 256, 256>>>(pre_x, pre_y, catpre);
    make_Mf_kernel<<<(G3_ * 64 + G3_ + 255) / 256, 256>>>(encWih, encEmbW, encEmbB, encBih, Mf, gibias);
    make_M1_kernel<<<(H_ * H_ + H_ + 255) / 256, 256>>>(decEmbW, decEmbB, outW, outB, M1, c1, c0fix);
    stack_copy_kernel<<<(G3_ * H_ + 255) / 256, 256>>>(decWih, decWhh, decBih, decBhh, Wstack, bstack);
    zero_h_kernel<<<(B_ * H_ + 255) / 256, 256>>>(hb[0]);
    make_attnprep_kernel<<<(128 * H_ + 255) / 256, 256>>>(attnW, attnB, M1, c0fix,
                                                          We_pad, Wh_pad, Wfuse, abias_pad, corr_l);
    make_wck_kernel<<<(H_ * 512 + 255) / 256, 256>>>(combW, combB, M1, c0fix, Wck, bias0c);

    // all-step parallel GEMMs
    run_mma128(catpre, 64, Mf, 64, gibias, GIenc, G3_, LPRE * B_, G3_, 64);
    run_mma64(fwd_x, fwd_x, 1 << 30, 32, nullptr, 1 << 30, 0,
              decEmbW + 16, 48, c1, nullptr, 0, Xe, H_, LFWD * B_, H_, 32, 0);
    run_mma128(Xe, 256, We_pad, 256, abias_pad, XL, 128, LFWD * B_, 128, 256);
    run_mma128(Xe, 256, combW, 512, nullptr, XC, 256, LFWD * B_, 256, 256);

    // ---- encoder: 60 steps ----
    int cur = 0;
    for (int t = 0; t < LPRE; t++) {
        run_mma64(hb[cur], hb[cur], 1 << 30, 256, nullptr, 1 << 30, 0,
                  encWhh, H_, encBhh, nullptr, 0, ghb, G3_, B_, G3_, H_, 0);
        gates_kernel<<<B_, 256>>>(GIenc + (size_t)t * B_ * G3_, G3_, ghb, G3_,
                                  hb[cur], hb[cur ^ 1], ENC + (size_t)t * B_ * H_);
        cur ^= 1;
    }

    // ---- decoder: 80 steps, 3 kernels each ----
    for (int t = 0; t < LFWD; t++) {
        if (t == 0) {
            attnstep_kernel<<<B_ / AROWS, 256>>>(nullptr, hb[cur], nullptr, nullptr,
                                                 Wh_pad, corr_l, XL, ENC, ctx);
        } else {
            attnstep_kernel<<<B_ / AROWS, 256>>>(gigh, hb[cur], hb[cur ^ 1],
                                                 Hall + (size_t)(t - 1) * B_ * H_,
                                                 Wfuse, nullptr, XL + (size_t)t * B_ * 128, ENC, ctx);
            cur ^= 1;
        }
        if (t == 0) {
            run_mma64(ctx, ctx, 1 << 30, 256, nullptr, 1 << 30, 0,
                      combW + 256, 512, bias0c, XC, 256, gbuf, H_, B_, H_, 256, 1);
        } else {
            run_mma64(ctx, ctx, 1 << 30, 256, hb[cur], 256, 256,
                      Wck, 512, combB, XC + (size_t)t * B_ * H_, 256,
                      gbuf, H_, B_, H_, 512, 1);
        }
        run_mma64(gbuf, hb[cur], G3_, 256, nullptr, 1 << 30, 0,
                  Wstack, H_, bstack, nullptr, 0, gigh, 2 * G3_, B_, 2 * G3_, H_, 0);
    }
    // final gates for t=79
    gates_kernel<<<B_, 256>>>(gigh, 2 * G3_, gigh + G3_, 2 * G3_,
                              hb[cur], hb[cur ^ 1], Hall + (size_t)(LFWD - 1) * B_ * H_);

    // ---- final outputs: ys = Hall @ out_W.T + out_b ----
    {
        dim3 grid(1, (LFWD * B_) / 64);
        gemm_kernel<<<grid, 256>>>(Hall, outW, H_, outB, out, 16, LFWD * B_, 16, H_);
    }
}

// round 7
// speedup vs baseline: 3.5125x; 3.5125x over previous
#include <cuda_runtime.h>
#include <cuda_bf16.h>
#include <cstdint>
#include <math.h>

#define B_      1024
#define H_      256
#define G3_     768
#define LPRE    60
#define LFWD    80
#define ML_     80

// ---------------- static device scratch (no allocation) ----------------
__device__ float g_catpre64[LPRE * B_ * 64];
__device__ float g_Mf64[G3_ * 64];
__device__ float g_gibias[G3_];
__device__ float g_GIenc[LPRE * B_ * G3_];
__device__ float g_ENC[LPRE * B_ * H_];
__device__ float g_M1[H_ * H_];
__device__ float g_c1[H_];
__device__ float g_c0fix[H_];
__device__ float g_Xe[LFWD * B_ * H_];
__device__ float g_Wstack[2 * G3_ * H_];
__device__ float g_bstack[2 * G3_];
__device__ float g_ctx[B_ * H_];
__device__ float g_logits[B_ * 128];
__device__ float g_g[B_ * H_];
__device__ float g_gigh[B_ * 2 * G3_];
__device__ float g_gh[B_ * G3_];
__device__ float g_hbuf[2][B_ * H_];
__device__ float g_Hall[LFWD * B_ * H_];
__device__ float g_We_pad[128 * H_];
__device__ float g_Wh_pad[128 * H_];
__device__ float g_Wfuse[128 * H_];
__device__ float g_abias_pad[128];
__device__ float g_corr_l[128];
__device__ float g_Wck[H_ * 512];
__device__ float g_bias0c[H_];
__device__ float g_XL[LFWD * B_ * 128];
__device__ float g_XC[LFWD * B_ * H_];

// ================= helpers =================
__device__ __forceinline__ uint32_t smem_u32(const void* p) {
    uint32_t a;
    asm("{ .reg .u64 t; cvta.to.shared.u64 t, %1; cvt.u32.u64 %0, t; }" : "=r"(a) : "l"(p));
    return a;
}

#define STS128(r0, r1, r2, r3, smem_addr) \
    asm volatile("st.shared.v4.b32 [%0], {%1, %2, %3, %4};" \
        :: "r"(smem_addr), "r"(r0), "r"(r1), "r"(r2), "r"(r3) : "memory")

#define LDSM4(r0, r1, r2, r3, addr) \
    asm volatile("ldmatrix.sync.aligned.m8n8.x4.shared.b16 {%0,%1,%2,%3}, [%4];" \
        : "=r"(r0), "=r"(r1), "=r"(r2), "=r"(r3) : "r"(addr))

#define MMA16816(d, a, b) \
    asm volatile("mma.sync.aligned.m16n8k16.row.col.f32.bf16.bf16.f32 " \
        "{%0,%1,%2,%3},{%4,%5,%6,%7},{%8,%9},{%0,%1,%2,%3};" \
        : "+f"((d)[0]), "+f"((d)[1]), "+f"((d)[2]), "+f"((d)[3]) \
        : "r"((a)[0]), "r"((a)[1]), "r"((a)[2]), "r"((a)[3]), "r"((b)[0]), "r"((b)[1]))

__device__ __forceinline__ void cvt_hl(float x, float y, uint32_t& h, uint32_t& l) {
    __nv_bfloat162 hb = __floats2bfloat162_rn(x, y);
    float rx = x - __low2float(hb);
    float ry = y - __high2float(hb);
    __nv_bfloat162 lb = __floats2bfloat162_rn(rx, ry);
    h = *reinterpret_cast<uint32_t*>(&hb);
    l = *reinterpret_cast<uint32_t*>(&lb);
}

__device__ __forceinline__ uint32_t swz(int r, int c) {
    return (uint32_t)(r * 64 + ((c ^ ((r >> 1) & 3)) << 4));
}

__device__ __forceinline__ void ldg16(const float* __restrict__ p, float* f) {
#pragma unroll
    for (int i = 0; i < 4; i++) {
        float4 v = *(const float4*)(p + 4 * i);
        f[4 * i + 0] = v.x; f[4 * i + 1] = v.y; f[4 * i + 2] = v.z; f[4 * i + 3] = v.w;
    }
}

__device__ __forceinline__ void sts_half(uint32_t sh, uint32_t sl, int row, int c0, const float* f) {
    uint32_t h[8], l[8];
#pragma unroll
    for (int i = 0; i < 8; i++) cvt_hl(f[2 * i], f[2 * i + 1], h[i], l[i]);
    uint32_t o0 = swz(row, c0), o1 = swz(row, c0 + 1);
    STS128(h[0], h[1], h[2], h[3], sh + o0);
    STS128(h[4], h[5], h[6], h[7], sh + o1);
    STS128(l[0], l[1], l[2], l[3], sl + o0);
    STS128(l[4], l[5], l[6], l[7], sl + o1);
}

// ================= BM=128 mma.sync bf16x3 GEMM (proven; dual-A + K-split) =============
#define MG_SMEM (2 * 32768)
#define OFF_AH 0u
#define OFF_AL 8192u
#define OFF_BH 16384u
#define OFF_BL 24576u

__global__ __launch_bounds__(256, 1) void mmagemm_kernel(
    const float* __restrict__ A0, const float* __restrict__ A1, int splitN, int lda0,
    const float* __restrict__ Ak, int ksplit, int ldak,
    const float* __restrict__ W, int ldw,
    const float* __restrict__ bias,
    const float* __restrict__ addmat, int ldadd,
    float* __restrict__ C, int ldc,
    int M, int N, int K, int act)
{
    extern __shared__ char dsm[];
    uint32_t sb = smem_u32(dsm);
    int tid = threadIdx.x, lane = tid & 31, wid = tid >> 5;
    int bm = blockIdx.y * 128, bn = blockIdx.x * 128;
    const float* __restrict__ A = (bn < splitN) ? A0 : A1;
    int warpM = wid & 3, warpN = wid >> 2;

    int lrow = tid >> 1, lhalf = tid & 1;
    const float* rowA = A + (size_t)(bm + lrow) * lda0 + lhalf * 16;
    const float* rowAk = Ak ? Ak + (size_t)(bm + lrow) * ldak + lhalf * 16 : nullptr;
    const float* bp = W + (size_t)(bn + lrow) * ldw + lhalf * 16;

    float acc[2][8][4];
#pragma unroll
    for (int i = 0; i < 2; i++)
#pragma unroll
        for (int j = 0; j < 8; j++)
#pragma unroll
            for (int q = 0; q < 4; q++) acc[i][j][q] = 0.f;

    float fa[16], fb[16];
    int nk = K >> 5;

    {
        const float* ap0 = (0 < ksplit) ? rowA : rowAk;
        ldg16(ap0, fa);
        ldg16(bp, fb);
        uint32_t st = sb;
        sts_half(st + OFF_AH, st + OFF_AL, lrow, lhalf * 2, fa);
        sts_half(st + OFF_BH, st + OFF_BL, lrow, lhalf * 2, fb);
    }
    __syncthreads();

    for (int i = 0; i < nk; i++) {
        if (i + 1 < nk) {
            int kk = (i + 1) * 32;
            const float* apn = (kk < ksplit) ? (rowA + kk) : (rowAk + (kk - ksplit));
            ldg16(apn, fa);
            ldg16(bp + (i + 1) * 32, fb);
        }
        uint32_t st = sb + (uint32_t)(i & 1) * 32768u;
#pragma unroll
        for (int ks = 0; ks < 2; ks++) {
            uint32_t ah[2][4], al[2][4], bh[8][2], bl[8][2];
#pragma unroll
            for (int mf = 0; mf < 2; mf++) {
                int r = warpM * 32 + mf * 16 + (lane & 15);
                int c = ks * 2 + (lane >> 4);
                uint32_t o = swz(r, c);
                LDSM4(ah[mf][0], ah[mf][1], ah[mf][2], ah[mf][3], st + OFF_AH + o);
                LDSM4(al[mf][0], al[mf][1], al[mf][2], al[mf][3], st + OFF_AL + o);
            }
#pragma unroll
            for (int p = 0; p < 4; p++) {
                int r = warpN * 64 + p * 16 + (lane & 7) + ((lane >> 4) << 3);
                int c = ks * 2 + ((lane >> 3) & 1);
                uint32_t o = swz(r, c);
                LDSM4(bh[2 * p][0], bh[2 * p][1], bh[2 * p + 1][0], bh[2 * p + 1][1], st + OFF_BH + o);
                LDSM4(bl[2 * p][0], bl[2 * p][1], bl[2 * p + 1][0], bl[2 * p + 1][1], st + OFF_BL + o);
            }
#pragma unroll
            for (int mf = 0; mf < 2; mf++)
#pragma unroll
                for (int nf = 0; nf < 8; nf++) {
                    MMA16816(acc[mf][nf], ah[mf], bh[nf]);
                    MMA16816(acc[mf][nf], ah[mf], bl[nf]);
                    MMA16816(acc[mf][nf], al[mf], bh[nf]);
                }
        }
        if (i + 1 < nk) {
            uint32_t st2 = sb + (uint32_t)((i + 1) & 1) * 32768u;
            sts_half(st2 + OFF_AH, st2 + OFF_AL, lrow, lhalf * 2, fa);
            sts_half(st2 + OFF_BH, st2 + OFF_BL, lrow, lhalf * 2, fb);
            __syncthreads();
        }
    }

#pragma unroll
    for (int mf = 0; mf < 2; mf++)
#pragma unroll
        for (int nf = 0; nf < 8; nf++) {
            int m0 = bm + warpM * 32 + mf * 16 + (lane >> 2);
            int n = bn + warpN * 64 + nf * 8 + (lane & 3) * 2;
            float b0 = 0.f, b1 = 0.f;
            if (bias) { b0 = bias[n]; b1 = bias[n + 1]; }
#pragma unroll
            for (int hh = 0; hh < 2; hh++) {
                int m = m0 + hh * 8;
                float v0 = acc[mf][nf][2 * hh] + b0;
                float v1 = acc[mf][nf][2 * hh + 1] + b1;
                if (addmat) {
                    const float* am = addmat + (size_t)m * ldadd + n;
                    v0 += am[0]; v1 += am[1];
                }
                if (act == 1) { v0 = tanhf(v0); v1 = tanhf(v1); }
                float2 vv = make_float2(v0, v1);
                *(float2*)(C + (size_t)m * ldc + n) = vv;
            }
        }
}

// ================= BM=64 mma GEMM (bisect target: small serial GEMMs only) ============
#define MG64_SMEM (2 * 24576)
#define O64_AH 0u
#define O64_AL 4096u
#define O64_BH 8192u
#define O64_BL 16384u

__global__ __launch_bounds__(256, 1) void mmagemm64_kernel(
    const float* __restrict__ A0, const float* __restrict__ A1, int splitN, int lda0,
    const float* __restrict__ Ak, int ksplit, int ldak,
    const float* __restrict__ W, int ldw,
    const float* __restrict__ bias,
    const float* __restrict__ addmat, int ldadd,
    float* __restrict__ C, int ldc,
    int M, int N, int K, int act)
{
    extern __shared__ char dsm[];
    uint32_t sb = smem_u32(dsm);
    int tid = threadIdx.x, lane = tid & 31, wid = tid >> 5;
    int bm = blockIdx.y * 64, bn = blockIdx.x * 128;
    const float* __restrict__ A = (bn < splitN) ? A0 : A1;
    int warpM = wid & 1, warpN = wid >> 1;

    int lrow = tid >> 1, lhalf = tid & 1;
    int arow = (tid & 127) >> 1;
    bool doA = tid < 128;
    const float* rowA = A + (size_t)(bm + arow) * lda0 + lhalf * 16;
    const float* rowAk = Ak ? Ak + (size_t)(bm + arow) * ldak + lhalf * 16 : nullptr;
    const float* bp = W + (size_t)(bn + lrow) * ldw + lhalf * 16;

    float acc[2][4][4];
#pragma unroll
    for (int i = 0; i < 2; i++)
#pragma unroll
        for (int j = 0; j < 4; j++)
#pragma unroll
            for (int q = 0; q < 4; q++) acc[i][j][q] = 0.f;

    float fa[16], fb[16];
    int nk = K >> 5;

    {
        ldg16(bp, fb);
        if (doA) {
            const float* ap0 = (0 < ksplit) ? rowA : rowAk;
            ldg16(ap0, fa);
        }
        sts_half(sb + O64_BH, sb + O64_BL, lrow, lhalf * 2, fb);
        if (doA) sts_half(sb + O64_AH, sb + O64_AL, arow, lhalf * 2, fa);
    }
    __syncthreads();

    for (int i = 0; i < nk; i++) {
        if (i + 1 < nk) {
            int kk = (i + 1) * 32;
            ldg16(bp + kk, fb);
            if (doA) {
                const float* apn = (kk < ksplit) ? (rowA + kk) : (rowAk + (kk - ksplit));
                ldg16(apn, fa);
            }
        }
        uint32_t st = sb + (uint32_t)(i & 1) * 24576u;
#pragma unroll
        for (int ks = 0; ks < 2; ks++) {
            uint32_t ah[2][4], al[2][4], bh[4][2], bl[4][2];
#pragma unroll
            for (int mf = 0; mf < 2; mf++) {
                int r = warpM * 32 + mf * 16 + (lane & 15);
                int c = ks * 2 + (lane >> 4);
                uint32_t o = swz(r, c);
                LDSM4(ah[mf][0], ah[mf][1], ah[mf][2], ah[mf][3], st + O64_AH + o);
                LDSM4(al[mf][0], al[mf][1], al[mf][2], al[mf][3], st + O64_AL + o);
            }
#pragma unroll
            for (int p = 0; p < 2; p++) {
                int r = warpN * 32 + p * 16 + (lane & 7) + ((lane >> 4) << 3);
                int c = ks * 2 + ((lane >> 3) & 1);
                uint32_t o = swz(r, c);
                LDSM4(bh[2 * p][0], bh[2 * p][1], bh[2 * p + 1][0], bh[2 * p + 1][1], st + O64_BH + o);
                LDSM4(bl[2 * p][0], bl[2 * p][1], bl[2 * p + 1][0], bl[2 * p + 1][1], st + O64_BL + o);
            }
#pragma unroll
            for (int mf = 0; mf < 2; mf++)
#pragma unroll
                for (int nf = 0; nf < 4; nf++) {
                    MMA16816(acc[mf][nf], ah[mf], bh[nf]);
                    MMA16816(acc[mf][nf], ah[mf], bl[nf]);
                    MMA16816(acc[mf][nf], al[mf], bh[nf]);
                }
        }
        if (i + 1 < nk) {
            uint32_t st2 = sb + (uint32_t)((i + 1) & 1) * 24576u;
            sts_half(st2 + O64_BH, st2 + O64_BL, lrow, lhalf * 2, fb);
            if (doA) sts_half(st2 + O64_AH, st2 + O64_AL, arow, lhalf * 2, fa);
            __syncthreads();
        }
    }

#pragma unroll
    for (int mf = 0; mf < 2; mf++)
#pragma unroll
        for (int nf = 0; nf < 4; nf++) {
            int m0 = bm + warpM * 32 + mf * 16 + (lane >> 2);
            int n = bn + warpN * 32 + nf * 8 + (lane & 3) * 2;
            float b0 = 0.f, b1 = 0.f;
            if (bias) { b0 = bias[n]; b1 = bias[n + 1]; }
#pragma unroll
            for (int hh = 0; hh < 2; hh++) {
                int m = m0 + hh * 8;
                float v0 = acc[mf][nf][2 * hh] + b0;
                float v1 = acc[mf][nf][2 * hh + 1] + b1;
                if (addmat) {
                    const float* am = addmat + (size_t)m * ldadd + n;
                    v0 += am[0]; v1 += am[1];
                }
                if (act == 1) { v0 = tanhf(v0); v1 = tanhf(v1); }
                float2 vv = make_float2(v0, v1);
                *(float2*)(C + (size_t)m * ldc + n) = vv;
            }
        }
}

// ---------------- SIMT fp32 GEMM (final output) ----------------
__global__ __launch_bounds__(256) void gemm_kernel(
    const float* __restrict__ A, const float* __restrict__ W, int ldw,
    const float* __restrict__ bias,
    float* __restrict__ C, int ldc,
    int M, int N, int K)
{
    __shared__ float As[16][64];
    __shared__ float Bs[16][64];
    int bn = blockIdx.x * 64;
    int bm = blockIdx.y * 64;

    int tid = threadIdx.x;
    int tx = tid & 15, ty = tid >> 4;
    int lr = tid >> 2;
    int lk = (tid & 3) * 4;

    float acc[4][4];
#pragma unroll
    for (int i = 0; i < 4; i++)
#pragma unroll
        for (int j = 0; j < 4; j++) acc[i][j] = 0.f;

    for (int k0 = 0; k0 < K; k0 += 16) {
        float4 a4 = *(const float4*)(A + (size_t)(bm + lr) * K + k0 + lk);
        As[lk + 0][lr] = a4.x; As[lk + 1][lr] = a4.y;
        As[lk + 2][lr] = a4.z; As[lk + 3][lr] = a4.w;
        float4 b4 = make_float4(0.f, 0.f, 0.f, 0.f);
        if (bn + lr < N)
            b4 = *(const float4*)(W + (size_t)(bn + lr) * ldw + k0 + lk);
        Bs[lk + 0][lr] = b4.x; Bs[lk + 1][lr] = b4.y;
        Bs[lk + 2][lr] = b4.z; Bs[lk + 3][lr] = b4.w;
        __syncthreads();
#pragma unroll
        for (int kk = 0; kk < 16; kk++) {
            float ra[4], rb[4];
#pragma unroll
            for (int i = 0; i < 4; i++) ra[i] = As[kk][ty * 4 + i];
#pragma unroll
            for (int j = 0; j < 4; j++) rb[j] = Bs[kk][tx * 4 + j];
#pragma unroll
            for (int i = 0; i < 4; i++)
#pragma unroll
                for (int j = 0; j < 4; j++) acc[i][j] += ra[i] * rb[j];
        }
        __syncthreads();
    }

#pragma unroll
    for (int i = 0; i < 4; i++) {
        int m = bm + ty * 4 + i;
#pragma unroll
        for (int j = 0; j < 4; j++) {
            int n = bn + tx * 4 + j;
            if (n < N)
                C[(size_t)m * ldc + n] = acc[i][j] + bias[n];
        }
    }
}

// ---------------- prep kernels ----------------
__global__ void pack_catpre_kernel(const float* __restrict__ px, const float* __restrict__ py,
                                   float* __restrict__ out)
{
    int idx = blockIdx.x * 256 + threadIdx.x;
    if (idx >= LPRE * B_ * 64) return;
    int c = idx & 63;
    int tb = idx >> 6;
    float v = 0.f;
    if (c < 32) v = px[(size_t)tb * 32 + c];
    else if (c < 48) v = py[(size_t)tb * 16 + (c - 32)];
    out[idx] = v;
}

__global__ void make_Mf_kernel(const float* __restrict__ Wih, const float* __restrict__ embW,
                               const float* __restrict__ embb, const float* __restrict__ bih,
                               float* __restrict__ Mf, float* __restrict__ gib)
{
    int idx = blockIdx.x * 256 + threadIdx.x;
    if (idx < G3_ * 64) {
        int i = idx >> 6, k = idx & 63;
        float s = 0.f;
        if (k < 48)
            for (int j = 0; j < H_; j++) s += Wih[(size_t)i * H_ + j] * embW[(size_t)j * 48 + k];
        Mf[idx] = s;
    } else if (idx < G3_ * 64 + G3_) {
        int i = idx - G3_ * 64;
        float s = bih[i];
        for (int j = 0; j < H_; j++) s += Wih[(size_t)i * H_ + j] * embb[j];
        gib[i] = s;
    }
}

__global__ void make_M1_kernel(const float* __restrict__ decEmbW, const float* __restrict__ decEmbb,
                               const float* __restrict__ outW, const float* __restrict__ outb,
                               float* __restrict__ M1, float* __restrict__ c1, float* __restrict__ c0fix)
{
    int idx = blockIdx.x * 256 + threadIdx.x;
    if (idx < H_ * H_) {
        int i = idx / H_, j = idx % H_;
        float s = 0.f;
        for (int k = 0; k < 16; k++) s += decEmbW[(size_t)i * 48 + k] * outW[(size_t)k * H_ + j];
        M1[idx] = s;
    } else if (idx < H_ * H_ + H_) {
        int i = idx - H_ * H_;
        float s = 0.f;
        for (int k = 0; k < 16; k++) s += decEmbW[(size_t)i * 48 + k] * outb[k];
        c1[i] = s + decEmbb[i];
        c0fix[i] = -s;
    }
}

__global__ void stack_copy_kernel(const float* __restrict__ Wih, const float* __restrict__ Whh,
                                  const float* __restrict__ bih, const float* __restrict__ bhh,
                                  float* __restrict__ Wst, float* __restrict__ bst)
{
    int idx = blockIdx.x * 256 + threadIdx.x;
    if (idx < G3_ * H_) {
        Wst[idx] = Wih[idx];
        Wst[G3_ * H_ + idx] = Whh[idx];
    }
    if (idx < G3_) { bst[idx] = bih[idx]; bst[G3_ + idx] = bhh[idx]; }
}

__global__ void zero_h_kernel(float* __restrict__ h)
{
    int idx = blockIdx.x * 256 + threadIdx.x;
    if (idx < B_ * H_) h[idx] = 0.f;
}

__global__ void make_attnprep_kernel(const float* __restrict__ attnW, const float* __restrict__ attnb,
                                     const float* __restrict__ M1, const float* __restrict__ c0fix,
                                     float* __restrict__ We_pad, float* __restrict__ Wh_pad,
                                     float* __restrict__ Wfuse, float* __restrict__ abias_pad,
                                     float* __restrict__ corr_l)
{
    int idx = blockIdx.x * 256 + threadIdx.x;
    if (idx >= 128 * H_) return;
    int m = idx >> 8, k = idx & 255;
    float we = 0.f, wh = 0.f, wf = 0.f;
    if (m < ML_) {
        we = attnW[(size_t)m * 512 + k];
        wh = attnW[(size_t)m * 512 + 256 + k];
        float s = wh;
        for (int j = 0; j < H_; j++) s += attnW[(size_t)m * 512 + j] * M1[(size_t)j * H_ + k];
        wf = s;
    }
    We_pad[idx] = we; Wh_pad[idx] = wh; Wfuse[idx] = wf;
    if (k == 0) {
        float ab = 0.f, cl = 0.f;
        if (m < ML_) {
            ab = attnb[m];
            for (int j = 0; j < H_; j++) cl += c0fix[j] * attnW[(size_t)m * 512 + j];
        }
        abias_pad[m] = ab;
        corr_l[m] = cl;
    }
}

__global__ void make_wck_kernel(const float* __restrict__ combW, const float* __restrict__ combb,
                                const float* __restrict__ M1, const float* __restrict__ c0fix,
                                float* __restrict__ Wck, float* __restrict__ bias0c)
{
    int idx = blockIdx.x * 256 + threadIdx.x;
    if (idx >= H_ * 512) return;
    int n = idx >> 9, k = idx & 511;
    float v;
    if (k < 256) {
        v = combW[(size_t)n * 512 + 256 + k];
    } else {
        float s = 0.f;
        int kk = k - 256;
        for (int j = 0; j < H_; j++) s += combW[(size_t)n * 512 + j] * M1[(size_t)j * H_ + kk];
        v = s;
    }
    Wck[idx] = v;
    if (k == 0) {
        float s = combb[n];
        for (int j = 0; j < H_; j++) s += combW[(size_t)n * 512 + j] * c0fix[j];
        bias0c[n] = s;
    }
}

// ---------------- GRU gates ----------------
__device__ __forceinline__ float sigm(float x) { return 1.f / (1.f + expf(-x)); }

__global__ __launch_bounds__(256) void gates_kernel(
    const float* __restrict__ gi, int ldgi,
    const float* __restrict__ gh, int ldgh,
    const float* __restrict__ h,
    float* __restrict__ h2, float* __restrict__ out2)
{
    int idx = blockIdx.x * 256 + threadIdx.x;
    int b = idx >> 8, j = idx & 255;
    const float* gib = gi + (size_t)b * ldgi;
    const float* ghb = gh + (size_t)b * ldgh;
    float r = sigm(gib[j] + ghb[j]);
    float z = sigm(gib[256 + j] + ghb[256 + j]);
    float n = tanhf(gib[512 + j] + r * ghb[512 + j]);
    float v = (1.f - z) * n + z * h[idx];
    h2[idx] = v;
    if (out2) out2[idx] = v;
}

// ---------------- softmax + context (per batch element) ----------------
__global__ __launch_bounds__(256) void smctx_kernel(
    const float* __restrict__ logits,
    const float* __restrict__ ENC,
    float* __restrict__ ctx)
{
    int b = blockIdx.x;
    __shared__ float saw[ML_];
    int tid = threadIdx.x;

    if (tid < 32) {
        const float* lb = logits + (size_t)b * 128;
        float x0 = lb[tid], x1 = lb[tid + 32];
        float x2 = (tid < 16) ? lb[tid + 64] : -1e30f;
        float mx = fmaxf(x0, fmaxf(x1, x2));
#pragma unroll
        for (int o = 16; o; o >>= 1) mx = fmaxf(mx, __shfl_xor_sync(0xffffffffu, mx, o));
        float e0 = expf(x0 - mx), e1 = expf(x1 - mx);
        float e2 = (tid < 16) ? expf(x2 - mx) : 0.f;
        float s = e0 + e1 + e2;
#pragma unroll
        for (int o = 16; o; o >>= 1) s += __shfl_xor_sync(0xffffffffu, s, o);
        float inv = 1.f / s;
        saw[tid] = e0 * inv;
        saw[tid + 32] = e1 * inv;
        if (tid < 16) saw[tid + 64] = e2 * inv;
    }
    __syncthreads();

    float acc = 0.f;
    const float* encb = ENC + (size_t)b * 256 + tid;
#pragma unroll 4
    for (int m = 0; m < LPRE; m++) acc += saw[m] * encb[(size_t)m * B_ * 256];
    ctx[(size_t)b * 256 + tid] = acc;
}

// ---------------- host launcher ----------------
static inline void run_mma(const float* A0, const float* A1, int splitN, int lda0,
                           const float* Ak, int ksplit, int ldak,
                           const float* W, int ldw, const float* bias,
                           const float* addmat, int ldadd,
                           float* C, int ldc, int M, int N, int K, int act)
{
    dim3 grid(N / 128, M / 128);
    mmagemm_kernel<<<grid, 256, MG_SMEM>>>(A0, A1, splitN, lda0, Ak, ksplit, ldak,
                                           W, ldw, bias, addmat, ldadd, C, ldc, M, N, K, act);
}

static inline void run_mma64(const float* A0, const float* A1, int splitN, int lda0,
                             const float* Ak, int ksplit, int ldak,
                             const float* W, int ldw, const float* bias,
                             const float* addmat, int ldadd,
                             float* C, int ldc, int M, int N, int K, int act)
{
    dim3 grid(N / 128, M / 64);
    mmagemm64_kernel<<<grid, 256, MG64_SMEM>>>(A0, A1, splitN, lda0, Ak, ksplit, ldak,
                                               W, ldw, bias, addmat, ldadd, C, ldc, M, N, K, act);
}

extern "C" void kernel_launch(void* const* d_in, const int* in_sizes, int n_in,
                              void* d_out, int out_size)
{
    const float* pre_x    = (const float*)d_in[0];
    const float* pre_y    = (const float*)d_in[1];
    const float* fwd_x    = (const float*)d_in[2];
    const float* encEmbW  = (const float*)d_in[3];
    const float* encEmbB  = (const float*)d_in[4];
    const float* encWih   = (const float*)d_in[5];
    const float* encWhh   = (const float*)d_in[6];
    const float* encBih   = (const float*)d_in[7];
    const float* encBhh   = (const float*)d_in[8];
    const float* decEmbW  = (const float*)d_in[9];
    const float* decEmbB  = (const float*)d_in[10];
    const float* attnW    = (const float*)d_in[11];
    const float* attnB    = (const float*)d_in[12];
    const float* combW    = (const float*)d_in[13];
    const float* combB    = (const float*)d_in[14];
    const float* decWih   = (const float*)d_in[15];
    const float* decWhh   = (const float*)d_in[16];
    const float* decBih   = (const float*)d_in[17];
    const float* decBhh   = (const float*)d_in[18];
    const float* outW     = (const float*)d_in[19];
    const float* outB     = (const float*)d_in[20];
    float* out = (float*)d_out;

    cudaFuncSetAttribute(mmagemm_kernel, cudaFuncAttributeMaxDynamicSharedMemorySize, MG_SMEM);
    cudaFuncSetAttribute(mmagemm64_kernel, cudaFuncAttributeMaxDynamicSharedMemorySize, MG64_SMEM);

    float *catpre, *Mf, *gibias, *GIenc, *ENC, *M1, *c1, *c0fix, *Xe;
    float *Wstack, *bstack, *ctx, *logits, *gbuf, *gigh, *ghb, *hb0, *hb1, *Hall;
    float *We_pad, *Wh_pad, *Wfuse, *abias_pad, *corr_l, *Wck, *bias0c, *XL, *XC;
    cudaGetSymbolAddress((void**)&catpre, g_catpre64);
    cudaGetSymbolAddress((void**)&Mf, g_Mf64);
    cudaGetSymbolAddress((void**)&gibias, g_gibias);
    cudaGetSymbolAddress((void**)&GIenc, g_GIenc);
    cudaGetSymbolAddress((void**)&ENC, g_ENC);
    cudaGetSymbolAddress((void**)&M1, g_M1);
    cudaGetSymbolAddress((void**)&c1, g_c1);
    cudaGetSymbolAddress((void**)&c0fix, g_c0fix);
    cudaGetSymbolAddress((void**)&Xe, g_Xe);
    cudaGetSymbolAddress((void**)&Wstack, g_Wstack);
    cudaGetSymbolAddress((void**)&bstack, g_bstack);
    cudaGetSymbolAddress((void**)&ctx, g_ctx);
    cudaGetSymbolAddress((void**)&logits, g_logits);
    cudaGetSymbolAddress((void**)&gbuf, g_g);
    cudaGetSymbolAddress((void**)&gigh, g_gigh);
    cudaGetSymbolAddress((void**)&ghb, g_gh);
    cudaGetSymbolAddress((void**)&hb0, g_hbuf);
    hb1 = hb0 + B_ * H_;
    cudaGetSymbolAddress((void**)&Hall, g_Hall);
    cudaGetSymbolAddress((void**)&We_pad, g_We_pad);
    cudaGetSymbolAddress((void**)&Wh_pad, g_Wh_pad);
    cudaGetSymbolAddress((void**)&Wfuse, g_Wfuse);
    cudaGetSymbolAddress((void**)&abias_pad, g_abias_pad);
    cudaGetSymbolAddress((void**)&corr_l, g_corr_l);
    cudaGetSymbolAddress((void**)&Wck, g_Wck);
    cudaGetSymbolAddress((void**)&bias0c, g_bias0c);
    cudaGetSymbolAddress((void**)&XL, g_XL);
    cudaGetSymbolAddress((void**)&XC, g_XC);

    float* hb[2] = {hb0, hb1};

    // ---- prep ----
    pack_catpre_kernel<<<(LPRE * B_ * 64 + 255) / 256, 256>>>(pre_x, pre_y, catpre);
    make_Mf_kernel<<<(G3_ * 64 + G3_ + 255) / 256, 256>>>(encWih, encEmbW, encEmbB, encBih, Mf, gibias);
    make_M1_kernel<<<(H_ * H_ + H_ + 255) / 256, 256>>>(decEmbW, decEmbB, outW, outB, M1, c1, c0fix);
    stack_copy_kernel<<<(G3_ * H_ + 255) / 256, 256>>>(decWih, decWhh, decBih, decBhh, Wstack, bstack);
    zero_h_kernel<<<(B_ * H_ + 255) / 256, 256>>>(hb[0]);
    make_attnprep_kernel<<<(128 * H_ + 255) / 256, 256>>>(attnW, attnB, M1, c0fix,
                                                          We_pad, Wh_pad, Wfuse, abias_pad, corr_l);
    make_wck_kernel<<<(H_ * 512 + 255) / 256, 256>>>(combW, combB, M1, c0fix, Wck, bias0c);

    // all-step parallel GEMMs (proven 128-kernel)
    run_mma(catpre, catpre, 1 << 30, 64, nullptr, 1 << 30, 0,
            Mf, 64, gibias, nullptr, 0, GIenc, G3_, LPRE * B_, G3_, 64, 0);
    run_mma(fwd_x, fwd_x, 1 << 30, 32, nullptr, 1 << 30, 0,
            decEmbW + 16, 48, c1, nullptr, 0, Xe, H_, LFWD * B_, H_, 32, 0);
    run_mma(Xe, Xe, 1 << 30, 256, nullptr, 1 << 30, 0,
            We_pad, 256, abias_pad, nullptr, 0, XL, 128, LFWD * B_, 128, 256, 0);
    run_mma(Xe, Xe, 1 << 30, 256, nullptr, 1 << 30, 0,
            combW, 512, nullptr, nullptr, 0, XC, 256, LFWD * B_, 256, 256, 0);

    // ---- encoder: 60 steps (gh GEMM on BM=64 -> 96 blocks) ----
    int cur = 0;
    for (int t = 0; t < LPRE; t++) {
        run_mma64(hb[cur], hb[cur], 1 << 30, 256, nullptr, 1 << 30, 0,
                  encWhh, H_, encBhh, nullptr, 0, ghb, G3_, B_, G3_, H_, 0);
        gates_kernel<<<B_, 256>>>(GIenc + (size_t)t * B_ * G3_, G3_, ghb, G3_,
                                  hb[cur], hb[cur ^ 1], ENC + (size_t)t * B_ * H_);
        cur ^= 1;
    }

    // ---- decoder: 80 steps, 5 kernels each (R4 structure) ----
    for (int t = 0; t < LFWD; t++) {
        // 1) logits (BM=64 -> 16 blocks)
        if (t == 0) {
            run_mma64(hb[cur], hb[cur], 1 << 30, 256, nullptr, 1 << 30, 0,
                      Wh_pad, 256, corr_l, XL, 128, logits, 128, B_, 128, 256, 0);
        } else {
            run_mma64(hb[cur], hb[cur], 1 << 30, 256, nullptr, 1 << 30, 0,
                      Wfuse, 256, nullptr, XL + (size_t)t * B_ * 128, 128,
                      logits, 128, B_, 128, 256, 0);
        }
        // 2) softmax + context
        smctx_kernel<<<B_, 256>>>(logits, ENC, ctx);
        // 3) comb (BM=64 -> 32 blocks)
        if (t == 0) {
            run_mma64(ctx, ctx, 1 << 30, 256, nullptr, 1 << 30, 0,
                      combW + 256, 512, bias0c, XC, 256, gbuf, H_, B_, H_, 256, 1);
        } else {
            run_mma64(ctx, ctx, 1 << 30, 256, hb[cur], 256, 256,
                      Wck, 512, combB, XC + (size_t)t * B_ * H_, 256,
                      gbuf, H_, B_, H_, 512, 1);
        }
        // 4) gigh (proven 128-kernel, 96 blocks)
        run_mma(gbuf, hb[cur], G3_, 256, nullptr, 1 << 30, 0,
                Wstack, H_, bstack, nullptr, 0, gigh, 2 * G3_, B_, 2 * G3_, H_, 0);
        // 5) gates
        gates_kernel<<<B_, 256>>>(gigh, 2 * G3_, gigh + G3_, 2 * G3_,
                                  hb[cur], hb[cur ^ 1], Hall + (size_t)t * B_ * H_);
        cur ^= 1;
    }

    // ---- final outputs: ys = Hall @ out_W.T + out_b ----
    {
        dim3 grid(1, (LFWD * B_) / 64);
        gemm_kernel<<<grid, 256>>>(Hall, outW, H_, outB, out, 16, LFWD * B_, 16, H_);
    }
}